// round 8
// baseline (speedup 1.0000x reference)
#include <cuda_runtime.h>
#include <math.h>
#include <stdint.h>

// Problem constants
#define BB 512
#define TT 128
#define DD 512
#define ALPHA 0.1f
#define EPSN 1e-5f

// Config: 64 clusters x 2 CTAs; cluster handles 8 batch rows; CTA owns 256 cols.
#define CSZ 2
#define GCTA 128
#define MPER 8
#define NT 1024
#define CPC 256          // columns per CTA
#define ARC 192          // A rows cached in smem (192*256*4 = 192KB); 192 = 6*32
#define NROW 32          // rows per thread (16 rq-blocks x 32 rows = 512)

typedef unsigned long long ull;

// ---- f32x2 helpers ----
static __device__ __forceinline__ ull packdup(float a) {
    ull r; asm("mov.b64 %0,{%1,%1};" : "=l"(r) : "f"(a)); return r;
}
static __device__ __forceinline__ void fma2(ull& d, ull a, ull b) {
    asm("fma.rn.f32x2 %0,%1,%2,%0;" : "+l"(d) : "l"(a), "l"(b));
}
static __device__ __forceinline__ float2 unpack2(ull v) {
    float2 f; asm("mov.b64 {%0,%1},%2;" : "=f"(f.x), "=f"(f.y) : "l"(v)); return f;
}
static __device__ __forceinline__ uint32_t s2u(const void* p) {
    uint32_t a;
    asm("{.reg .u64 t; cvta.to.shared.u64 t,%1; cvt.u32.u64 %0,t;}" : "=r"(a) : "l"(p));
    return a;
}

// ---- cluster mbarrier ops ----
static __device__ __forceinline__ void mbar_init(uint32_t a, uint32_t n) {
    asm volatile("mbarrier.init.shared.b64 [%0],%1;" :: "r"(a), "r"(n) : "memory");
}
static __device__ __forceinline__ void remote_st_f32(uint32_t a, uint32_t rk, float v) {
    asm volatile("{.reg .b32 r; mapa.shared::cluster.u32 r,%1,%2; st.shared::cluster.f32 [r],%0;}"
                 :: "f"(v), "r"(a), "r"(rk) : "memory");
}
static __device__ __forceinline__ void remote_arrive_rel(uint32_t a, uint32_t rk) {
    asm volatile("{.reg .b32 r; mapa.shared::cluster.u32 r,%0,%1;"
                 " mbarrier.arrive.release.cluster.shared::cluster.b64 _,[r];}"
                 :: "r"(a), "r"(rk) : "memory");
}
static __device__ __forceinline__ void mbar_wait_acq(uint32_t a, uint32_t ph) {
    asm volatile("{\n\t.reg .pred P;\n"
                 "W%=:\n\tmbarrier.try_wait.parity.acquire.cluster.shared::cta.b64 P,[%0],%1;\n"
                 "\t@P bra D%=;\n\tbra W%=;\nD%=:\n\t}"
                 :: "r"(a), "r"(ph) : "memory");
}

// fast sincos with explicit 2*pi range reduction
static __device__ __forceinline__ void fsincos(float th, float* s, float* c) {
    const float INV2PI = 0.15915494309189535f;
    const float TWOPI  = 6.283185307179586f;
    th = fmaf(-TWOPI, rintf(th * INV2PI), th);
    __sincosf(th, s, c);
}

// 16 packed FMAs: one A row (4 cols) against 8 m-values of zx
static __device__ __forceinline__ void rowfma(ull* acc, float4 b, const float* zrow) {
    ulonglong2 za = *(const ulonglong2*)(zrow);
    ulonglong2 zb = *(const ulonglong2*)(zrow + 4);
    ull z0 = za.x, z1 = za.y, z2 = zb.x, z3 = zb.y;
    ull d;
    d = packdup(b.x);
    fma2(acc[0], z0, d); fma2(acc[1], z1, d); fma2(acc[2], z2, d); fma2(acc[3], z3, d);
    d = packdup(b.y);
    fma2(acc[4], z0, d); fma2(acc[5], z1, d); fma2(acc[6], z2, d); fma2(acc[7], z3, d);
    d = packdup(b.z);
    fma2(acc[8], z0, d); fma2(acc[9], z1, d); fma2(acc[10], z2, d); fma2(acc[11], z3, d);
    d = packdup(b.w);
    fma2(acc[12], z0, d); fma2(acc[13], z1, d); fma2(acc[14], z2, d); fma2(acc[15], z3, d);
}

__global__ void __launch_bounds__(NT, 1) __cluster_dims__(CSZ, 1, 1)
can_r8_kernel(const float* __restrict__ dx_pi,   // [B,T,2]
              const float* __restrict__ z0,      // [B,D]
              const float* __restrict__ x0,      // [B,2]
              const float* __restrict__ omega,   // [K,2]
              const float* __restrict__ Ag,      // [D,D]
              const float* __restrict__ z0b,     // [D]
              float* __restrict__ out_z,         // [B,T,D]
              float* __restrict__ out_x)         // [B,T,2]
{
    extern __shared__ __align__(16) float As[];          // ARC*CPC = 192KB

    __shared__ __align__(16) float zx_s[DD][MPER];       // 16KB
    __shared__ float red_s[32][16];                      // 2KB
    __shared__ float nrm_s[16];
    __shared__ float x_s[MPER][2];
    __shared__ float dxt_s[MPER][2];
    __shared__ float peer_s[2][16];
    __shared__ __align__(8) ull mbar[2];
    __shared__ float scale_s;

    const int t    = threadIdx.x;
    const int lane = t & 31;
    const int wid  = t >> 5;
    const int rank = (int)(blockIdx.x & 1);
    const int prk  = rank ^ 1;
    const int colbase = rank * CPC;
    const int base = (int)(blockIdx.x >> 1) * MPER;

    // mainloop mapping: 64 col-groups (4 cols) x 16 row-blocks (32 rows each)
    const int cg = t & 63;
    const int rq = t >> 6;

    // ---- preload A rows [0,ARC) cols [colbase,+256) into smem ----
    {
        const float4* src = (const float4*)Ag;
        float4* dst = (float4*)As;
        const int n4 = ARC * CPC / 4;
        for (int idx = t; idx < n4; idx += NT) {
            int row = idx >> 6;
            int f4  = idx & 63;
            dst[idx] = src[row * (DD / 4) + (colbase >> 2) + f4];
        }
    }
    if (t == 0) { mbar_init(s2u(&mbar[0]), 16); mbar_init(s2u(&mbar[1]), 16); }

    // ---- ||z0_base|| (first 512 threads) ----
    if (t < 512) {
        float v = z0b[t]; v *= v;
        #pragma unroll
        for (int o = 16; o; o >>= 1) v += __shfl_xor_sync(0xFFFFFFFFu, v, o);
        if (lane == 0) nrm_s[wid] = v;
    }
    if (t < MPER * 2) x_s[t >> 1][t & 1] = x0[(base + (t >> 1)) * 2 + (t & 1)];
    __syncthreads();
    if (t == 0) {
        float s = 0.f;
        #pragma unroll
        for (int w = 0; w < 16; w++) s += nrm_s[w];
        scale_s = 1.0f / (sqrtf(s) + EPSN);
    }
    __syncthreads();

    // peer mbarriers initialized before any remote arrive
    asm volatile("barrier.cluster.arrive.aligned;" ::: "memory");
    asm volatile("barrier.cluster.wait.aligned;" ::: "memory");

    // ---- per-thread constants ----
    // phase 1: block k1, m-pair mq (m = 2mq, 2mq+1)
    const int k1 = t & 255;
    const int mq = t >> 8;               // 0..3
    const float omA0 = omega[2 * k1];
    const float omA1 = omega[2 * k1 + 1];
    const float p0 = z0b[2 * k1] * scale_s;
    const float p1 = z0b[2 * k1 + 1] * scale_s;

    // gradient epilogue: this thread's 4 cols = blocks kb0, kb0+1
    const int kb0 = rank * 128 + 2 * cg;
    const float omG00 = omega[2 * kb0],     omG01 = omega[2 * kb0 + 1];
    const float omG10 = omega[2 * kb0 + 2], omG11 = omega[2 * kb0 + 3];

    // phase 4: column gcol, m-pair mp (m = mp, mp+1)
    const int gcol = colbase + (t & 255);
    const int mp   = (t >> 8) * 2;
    const float omB0 = omega[2 * (gcol >> 1)];
    const float omB1 = omega[2 * (gcol >> 1) + 1];

    // output slot for the folded butterfly: bitrev4(lane & 15)
    const int brl = ((lane & 1) << 3) | ((lane & 2) << 1) |
                    ((lane & 4) >> 1) | ((lane & 8) >> 3);

    float zc0 = z0[(base + mp) * DD + gcol];
    float zc1 = z0[(base + mp + 1) * DD + gcol];

    const float4* As4 = (const float4*)As;                       // [row][64]
    const float4* Ag4 = (const float4*)Ag + (colbase >> 2) + cg; // row stride 128
    const int r0 = rq * NROW;                                    // block start
    const bool cached = (rq < 6);                                // rows < 192

    for (int ts = 0; ts < TT; ts++) {
        // ---- phase 1: zx = T(x_m) z0b_hat (2 m per thread) ----
        {
            float u0[2], u1[2];
            #pragma unroll
            for (int mm = 0; mm < 2; mm++) {
                int m = 2 * mq + mm;
                float th = fmaf(omA0, x_s[m][0], omA1 * x_s[m][1]);
                float s, ccv; fsincos(th, &s, &ccv);
                u0[mm] = fmaf(ccv, p0, -s * p1);
                u1[mm] = fmaf(s, p0, ccv * p1);
            }
            *(float2*)&zx_s[2 * k1][2 * mq]     = make_float2(u0[0], u0[1]);
            *(float2*)&zx_s[2 * k1 + 1][2 * mq] = make_float2(u1[0], u1[1]);
        }
        __syncthreads();   // sync A: zx ready

        // ---- phase 2: partial w over 32 rows x 4 cols x 8 m ----
        ull acc[16];
        #pragma unroll
        for (int q = 0; q < 16; q++) acc[q] = 0ull;

        if (cached) {
            #pragma unroll 2
            for (int i = r0; i < r0 + NROW; i += 4) {
                float4 b0 = As4[(i + 0) * 64 + cg];
                float4 b1 = As4[(i + 1) * 64 + cg];
                float4 b2 = As4[(i + 2) * 64 + cg];
                float4 b3 = As4[(i + 3) * 64 + cg];
                rowfma(acc, b0, &zx_s[i + 0][0]);
                rowfma(acc, b1, &zx_s[i + 1][0]);
                rowfma(acc, b2, &zx_s[i + 2][0]);
                rowfma(acc, b3, &zx_s[i + 3][0]);
            }
        } else {
            #pragma unroll 2
            for (int i = r0; i < r0 + NROW; i += 4) {
                float4 b0 = __ldg(&Ag4[(i + 0) * (DD / 4)]);
                float4 b1 = __ldg(&Ag4[(i + 1) * (DD / 4)]);
                float4 b2 = __ldg(&Ag4[(i + 2) * (DD / 4)]);
                float4 b3 = __ldg(&Ag4[(i + 3) * (DD / 4)]);
                rowfma(acc, b0, &zx_s[i + 0][0]);
                rowfma(acc, b1, &zx_s[i + 1][0]);
                rowfma(acc, b2, &zx_s[i + 2][0]);
                rowfma(acc, b3, &zx_s[i + 3][0]);
            }
        }

        // ---- gradient epilogue: fold partial w into r16 (float2 zx loads) ----
        float r16[16];
        {
            const int g0 = colbase + 4 * cg;
            #pragma unroll
            for (int p = 0; p < 4; p++) {
                float2 ze2 = *(const float2*)&zx_s[g0][2 * p];
                float2 zo2 = *(const float2*)&zx_s[g0 + 1][2 * p];
                float2 w0 = unpack2(acc[p]);
                float2 w1 = unpack2(acc[4 + p]);
                float gA0 = ze2.x * w1.x - zo2.x * w0.x;
                float gA1 = ze2.y * w1.y - zo2.y * w0.y;
                r16[4 * p]     = omG00 * gA0;
                r16[4 * p + 1] = omG01 * gA0;
                r16[4 * p + 2] = omG00 * gA1;
                r16[4 * p + 3] = omG01 * gA1;
            }
            #pragma unroll
            for (int p = 0; p < 4; p++) {
                float2 zf2 = *(const float2*)&zx_s[g0 + 2][2 * p];
                float2 zg2 = *(const float2*)&zx_s[g0 + 3][2 * p];
                float2 w2 = unpack2(acc[8 + p]);
                float2 w3 = unpack2(acc[12 + p]);
                float gB0 = zf2.x * w3.x - zg2.x * w2.x;
                float gB1 = zf2.y * w3.y - zg2.y * w2.y;
                r16[4 * p]     = fmaf(omG10, gB0, r16[4 * p]);
                r16[4 * p + 1] = fmaf(omG11, gB0, r16[4 * p + 1]);
                r16[4 * p + 2] = fmaf(omG10, gB1, r16[4 * p + 2]);
                r16[4 * p + 3] = fmaf(omG11, gB1, r16[4 * p + 3]);
            }
        }

        // ---- folding butterfly: 16 values x 32 lanes -> 1/lane (16 SHFL) ----
        {
            #pragma unroll
            for (int o = 1, v = 16; o <= 8; o <<= 1, v >>= 1) {
                const bool hi = (lane & o) != 0;
                #pragma unroll
                for (int i = 0; i < v / 2; i++) {
                    float send = hi ? r16[i] : r16[i + v / 2];
                    float recv = __shfl_xor_sync(0xFFFFFFFFu, send, o);
                    float keep = hi ? r16[i + v / 2] : r16[i];
                    r16[i] = keep + recv;
                }
            }
            r16[0] += __shfl_xor_sync(0xFFFFFFFFu, r16[0], 16);
        }
        if (lane < 16) red_s[wid][brl] = r16[0];
        __syncthreads();   // sync B: red ready

        // ---- cross-CTA exchange of 16 dx partials ----
        const int buf = ts & 1;
        const uint32_t ph = (uint32_t)((ts >> 1) & 1);
        if (t < 16) {
            float v = 0.f;
            #pragma unroll
            for (int w = 0; w < 32; w++) v += red_s[w][t];
            remote_st_f32(s2u(&peer_s[buf][t]), (uint32_t)prk, v);
            remote_arrive_rel(s2u(&mbar[buf]), (uint32_t)prk);
            mbar_wait_acq(s2u(&mbar[buf]), ph);
            float tot = v + peer_s[buf][t];
            const int m = t >> 1, j = t & 1;
            float dxt = dx_pi[((base + m) * TT + ts) * 2 + j] + ALPHA * tot;
            dxt_s[m][j] = dxt;
            float xn = x_s[m][j] + dxt;
            xn = fminf(fmaxf(xn, 0.0f), 2.0f);    // BOX_W == BOX_H == 2
            x_s[m][j] = xn;
            out_x[((base + m) * TT + ts) * 2 + j] = xn;
        }
        __syncthreads();   // sync C: dxt ready

        // ---- phase 4: carried z' = T(dx_total) z (2 m per thread) ----
        {
            float th0 = fmaf(omB0, dxt_s[mp][0],     omB1 * dxt_s[mp][1]);
            float th1 = fmaf(omB0, dxt_s[mp + 1][0], omB1 * dxt_s[mp + 1][1]);
            float s0, c0, s1, c1;
            fsincos(th0, &s0, &c0);
            fsincos(th1, &s1, &c1);
            float zp0 = __shfl_xor_sync(0xFFFFFFFFu, zc0, 1);
            float zp1 = __shfl_xor_sync(0xFFFFFFFFu, zc1, 1);
            float zn0, zn1;
            if (gcol & 1) {
                zn0 = fmaf(s0, zp0, c0 * zc0);
                zn1 = fmaf(s1, zp1, c1 * zc1);
            } else {
                zn0 = fmaf(c0, zc0, -s0 * zp0);
                zn1 = fmaf(c1, zc1, -s1 * zp1);
            }
            zc0 = zn0; zc1 = zn1;
            out_z[((size_t)(base + mp) * TT + ts) * DD + gcol]     = zn0;
            out_z[((size_t)(base + mp + 1) * TT + ts) * DD + gcol] = zn1;
        }
        // next phase-1 zx_s write is ordered after all zx reads by sync B + C
    }
}

extern "C" void kernel_launch(void* const* d_in, const int* in_sizes, int n_in,
                              void* d_out, int out_size) {
    (void)in_sizes; (void)n_in; (void)out_size;
    const float* dx_pi = (const float*)d_in[0];   // [512,128,2]
    const float* z0    = (const float*)d_in[1];   // [512,512]
    const float* x0    = (const float*)d_in[2];   // [512,2]
    const float* omega = (const float*)d_in[3];   // [256,2]
    const float* Ag    = (const float*)d_in[4];   // [512,512]
    const float* z0b   = (const float*)d_in[5];   // [512]

    float* out_z = (float*)d_out;                       // [512,128,512]
    float* out_x = out_z + (size_t)BB * TT * DD;        // [512,128,2]

    const size_t shmem = (size_t)ARC * CPC * sizeof(float);   // 192 KB dynamic
    cudaFuncSetAttribute(can_r8_kernel,
                         cudaFuncAttributeMaxDynamicSharedMemorySize, (int)shmem);
    can_r8_kernel<<<GCTA, NT, shmem>>>(dx_pi, z0, x0, omega, Ag, z0b,
                                       out_z, out_x);
}

// round 9
// speedup vs baseline: 1.5412x; 1.5412x over previous
#include <cuda_runtime.h>
#include <math.h>
#include <stdint.h>

// Problem constants
#define BB 512
#define TT 128
#define DD 512
#define ALPHA 0.1f
#define EPSN 1e-5f

// Config: 64 clusters x 2 CTAs; cluster handles 8 batch rows; CTA owns 256 cols.
#define CSZ 2
#define GCTA 128
#define MPER 8
#define NT 512
#define CPC 256          // columns per CTA
#define ARC 128          // A rows cached in smem (128*256*4 = 128KB); rq0,rq1 cached
#define NSEG 7           // combine segments (rq 1..7)
#define CSLOT (NSEG*64)  // 448 slots

typedef unsigned long long ull;

// ---- f32x2 helpers ----
static __device__ __forceinline__ ull packdup(float a) {
    ull r; asm("mov.b64 %0,{%1,%1};" : "=l"(r) : "f"(a)); return r;
}
static __device__ __forceinline__ void fma2(ull& d, ull a, ull b) {
    asm("fma.rn.f32x2 %0,%1,%2,%0;" : "+l"(d) : "l"(a), "l"(b));
}
static __device__ __forceinline__ ull add2(ull a, ull b) {
    ull r; asm("add.rn.f32x2 %0,%1,%2;" : "=l"(r) : "l"(a), "l"(b)); return r;
}
static __device__ __forceinline__ float2 unpack2(ull v) {
    float2 f; asm("mov.b64 {%0,%1},%2;" : "=f"(f.x), "=f"(f.y) : "l"(v)); return f;
}
static __device__ __forceinline__ uint32_t s2u(const void* p) {
    uint32_t a;
    asm("{.reg .u64 t; cvta.to.shared.u64 t,%1; cvt.u32.u64 %0,t;}" : "=r"(a) : "l"(p));
    return a;
}

// ---- cluster mbarrier ops ----
static __device__ __forceinline__ void mbar_init(uint32_t a, uint32_t n) {
    asm volatile("mbarrier.init.shared.b64 [%0],%1;" :: "r"(a), "r"(n) : "memory");
}
static __device__ __forceinline__ void remote_st_f32(uint32_t a, uint32_t rk, float v) {
    asm volatile("{.reg .b32 r; mapa.shared::cluster.u32 r,%1,%2; st.shared::cluster.f32 [r],%0;}"
                 :: "f"(v), "r"(a), "r"(rk) : "memory");
}
static __device__ __forceinline__ void remote_arrive_rel(uint32_t a, uint32_t rk) {
    asm volatile("{.reg .b32 r; mapa.shared::cluster.u32 r,%0,%1;"
                 " mbarrier.arrive.release.cluster.shared::cluster.b64 _,[r];}"
                 :: "r"(a), "r"(rk) : "memory");
}
static __device__ __forceinline__ void mbar_wait_acq(uint32_t a, uint32_t ph) {
    asm volatile("{\n\t.reg .pred P;\n"
                 "W%=:\n\tmbarrier.try_wait.parity.acquire.cluster.shared::cta.b64 P,[%0],%1;\n"
                 "\t@P bra D%=;\n\tbra W%=;\nD%=:\n\t}"
                 :: "r"(a), "r"(ph) : "memory");
}

// fast sincos with explicit 2*pi range reduction
static __device__ __forceinline__ void fsincos(float th, float* s, float* c) {
    const float INV2PI = 0.15915494309189535f;
    const float TWOPI  = 6.283185307179586f;
    th = fmaf(-TWOPI, rintf(th * INV2PI), th);
    __sincosf(th, s, c);
}

// 16 packed FMAs: one A row (4 cols) against 8 m-values of zx
static __device__ __forceinline__ void rowfma(ull* acc, float4 b, const float* zrow) {
    ulonglong2 za = *(const ulonglong2*)(zrow);
    ulonglong2 zb = *(const ulonglong2*)(zrow + 4);
    ull z0 = za.x, z1 = za.y, z2 = zb.x, z3 = zb.y;
    ull d;
    d = packdup(b.x);
    fma2(acc[0], z0, d); fma2(acc[1], z1, d); fma2(acc[2], z2, d); fma2(acc[3], z3, d);
    d = packdup(b.y);
    fma2(acc[4], z0, d); fma2(acc[5], z1, d); fma2(acc[6], z2, d); fma2(acc[7], z3, d);
    d = packdup(b.z);
    fma2(acc[8], z0, d); fma2(acc[9], z1, d); fma2(acc[10], z2, d); fma2(acc[11], z3, d);
    d = packdup(b.w);
    fma2(acc[12], z0, d); fma2(acc[13], z1, d); fma2(acc[14], z2, d); fma2(acc[15], z3, d);
}

__global__ void __launch_bounds__(NT, 1) __cluster_dims__(CSZ, 1, 1)
can_r9_kernel(const float* __restrict__ dx_pi,   // [B,T,2]
              const float* __restrict__ z0,      // [B,D]
              const float* __restrict__ x0,      // [B,2]
              const float* __restrict__ omega,   // [K,2]
              const float* __restrict__ Ag,      // [D,D]
              const float* __restrict__ z0b,     // [D]
              float* __restrict__ out_z,         // [B,T,D]
              float* __restrict__ out_x)         // [B,T,2]
{
    // dynamic smem: As (128KB) then cbuf (56KB)
    extern __shared__ __align__(16) float As[];
    ulonglong2* cbuf = (ulonglong2*)(As + ARC * CPC);   // [8][CSLOT]

    __shared__ __align__(16) float zx_s[DD][MPER];      // 16KB
    __shared__ float red_s[2][16];
    __shared__ float nrm_s[16];
    __shared__ float x_s[MPER][2];
    __shared__ float dxt_s[MPER][2];
    __shared__ float peer_s[2][16];
    __shared__ __align__(8) ull mbar[2];
    __shared__ float scale_s;

    const int t    = threadIdx.x;
    const int lane = t & 31;
    const int wid  = t >> 5;
    const int rank = (int)(blockIdx.x & 1);
    const int prk  = rank ^ 1;
    const int colbase = rank * CPC;
    const int base = (int)(blockIdx.x >> 1) * MPER;

    // mainloop mapping: 64 col-groups (4 cols) x 8 row-blocks (64 rows)
    const int cg = t & 63;
    const int rq = t >> 6;

    // ---- preload A rows [0,ARC) cols [colbase,+256) into smem ----
    {
        const float4* src = (const float4*)Ag;
        float4* dst = (float4*)As;
        const int n4 = ARC * CPC / 4;
        for (int idx = t; idx < n4; idx += NT) {
            int row = idx >> 6;
            int f4  = idx & 63;
            dst[idx] = src[row * (DD / 4) + (colbase >> 2) + f4];
        }
    }
    if (t == 0) { mbar_init(s2u(&mbar[0]), 16); mbar_init(s2u(&mbar[1]), 16); }

    // ---- ||z0_base|| ----
    {
        float v = z0b[t]; v *= v;
        #pragma unroll
        for (int o = 16; o; o >>= 1) v += __shfl_xor_sync(0xFFFFFFFFu, v, o);
        if (lane == 0) nrm_s[wid] = v;
    }
    if (t < MPER * 2) x_s[t >> 1][t & 1] = x0[(base + (t >> 1)) * 2 + (t & 1)];
    __syncthreads();
    if (t == 0) {
        float s = 0.f;
        #pragma unroll
        for (int w = 0; w < 16; w++) s += nrm_s[w];
        scale_s = 1.0f / (sqrtf(s) + EPSN);
    }
    __syncthreads();

    // peer mbarriers initialized before any remote arrive
    asm volatile("barrier.cluster.arrive.aligned;" ::: "memory");
    asm volatile("barrier.cluster.wait.aligned;" ::: "memory");

    // ---- per-thread constants ----
    const int k1 = t & 255;
    const int mh = t >> 8;
    const float omA0 = omega[2 * k1];
    const float omA1 = omega[2 * k1 + 1];
    const float p0 = z0b[2 * k1] * scale_s;
    const float p1 = z0b[2 * k1 + 1] * scale_s;

    const int kb0 = rank * 128 + 2 * cg;
    const float omG00 = omega[2 * kb0],     omG01 = omega[2 * kb0 + 1];
    const float omG10 = omega[2 * kb0 + 2], omG11 = omega[2 * kb0 + 3];

    const int gcol = colbase + (t & 255);
    const int mg4  = (t >> 8) * 4;
    const float omB0 = omega[2 * (gcol >> 1)];
    const float omB1 = omega[2 * (gcol >> 1) + 1];

    float zc[4];
    #pragma unroll
    for (int mm = 0; mm < 4; mm++)
        zc[mm] = z0[(base + mg4 + mm) * DD + gcol];

    const float4* As4 = (const float4*)As;                       // [row][64]
    const float4* Ag4 = (const float4*)Ag + (colbase >> 2) + cg; // row stride 128
    const int r0 = rq * 64;
    const bool cached = (rq < 2);          // rows 0..127 in smem

    for (int ts = 0; ts < TT; ts++) {
        // ---- prefetch first 2 streamed batches (independent of zx/x) ----
        float4 buf0[4], buf1[4];
        if (!cached) {
            #pragma unroll
            for (int q = 0; q < 4; q++) buf0[q] = __ldg(&Ag4[(r0 + q) * (DD / 4)]);
            #pragma unroll
            for (int q = 0; q < 4; q++) buf1[q] = __ldg(&Ag4[(r0 + 4 + q) * (DD / 4)]);
        }

        // ---- phase 1: zx = T(x_m) z0b_hat ----
        {
            float u0[4], u1[4];
            #pragma unroll
            for (int mm = 0; mm < 4; mm++) {
                int m = mh * 4 + mm;
                float th = fmaf(omA0, x_s[m][0], omA1 * x_s[m][1]);
                float s, ccv; fsincos(th, &s, &ccv);
                u0[mm] = fmaf(ccv, p0, -s * p1);
                u1[mm] = fmaf(s, p0, ccv * p1);
            }
            *(float4*)&zx_s[2 * k1][mh * 4]     = make_float4(u0[0], u0[1], u0[2], u0[3]);
            *(float4*)&zx_s[2 * k1 + 1][mh * 4] = make_float4(u1[0], u1[1], u1[2], u1[3]);
        }
        __syncthreads();   // sync A: zx ready

        // ---- phase 2: partial w over this thread's 64 rows x 4 cols x 8 m ----
        ull acc[16];
        #pragma unroll
        for (int q = 0; q < 16; q++) acc[q] = 0ull;

        if (cached) {
            // pure-LDS warps
            #pragma unroll 4
            for (int i = r0; i < r0 + 64; i += 4) {
                float4 b0 = As4[(i + 0) * 64 + cg];
                float4 b1 = As4[(i + 1) * 64 + cg];
                float4 b2 = As4[(i + 2) * 64 + cg];
                float4 b3 = As4[(i + 3) * 64 + cg];
                rowfma(acc, b0, &zx_s[i + 0][0]);
                rowfma(acc, b1, &zx_s[i + 1][0]);
                rowfma(acc, b2, &zx_s[i + 2][0]);
                rowfma(acc, b3, &zx_s[i + 3][0]);
            }
        } else {
            // pure-LDG warps: depth-2 software pipeline over 16 batches of 4 rows
            #pragma unroll
            for (int b = 0; b < 16; b++) {
                const int i = r0 + 4 * b;
                // move current batch to compute regs
                float4 c0, c1, c2, c3;
                if ((b & 1) == 0) { c0 = buf0[0]; c1 = buf0[1]; c2 = buf0[2]; c3 = buf0[3]; }
                else              { c0 = buf1[0]; c1 = buf1[1]; c2 = buf1[2]; c3 = buf1[3]; }
                // issue loads for batch b+2 into the freed buffer
                if (b < 14) {
                    const int ip = i + 8;
                    if ((b & 1) == 0) {
                        #pragma unroll
                        for (int q = 0; q < 4; q++)
                            buf0[q] = __ldg(&Ag4[(ip + q) * (DD / 4)]);
                    } else {
                        #pragma unroll
                        for (int q = 0; q < 4; q++)
                            buf1[q] = __ldg(&Ag4[(ip + q) * (DD / 4)]);
                    }
                }
                rowfma(acc, c0, &zx_s[i + 0][0]);
                rowfma(acc, c1, &zx_s[i + 1][0]);
                rowfma(acc, c2, &zx_s[i + 2][0]);
                rowfma(acc, c3, &zx_s[i + 3][0]);
            }
        }

        // ---- combine blocks into rq0 ----
        if (rq >= 1) {
            const int slot = (rq - 1) * 64 + cg;
            #pragma unroll
            for (int j = 0; j < 8; j++)
                cbuf[j * CSLOT + slot] = make_ulonglong2(acc[2 * j], acc[2 * j + 1]);
        }
        __syncthreads();   // sync: partials staged

        if (rq == 0) {
            #pragma unroll
            for (int seg = 0; seg < NSEG; seg++) {
                const int slot = seg * 64 + cg;
                #pragma unroll
                for (int j = 0; j < 8; j++) {
                    ulonglong2 v = cbuf[j * CSLOT + slot];
                    acc[2 * j]     = add2(acc[2 * j], v.x);
                    acc[2 * j + 1] = add2(acc[2 * j + 1], v.y);
                }
            }
            float w[4][8];
            #pragma unroll
            for (int cc2 = 0; cc2 < 4; cc2++) {
                #pragma unroll
                for (int p = 0; p < 4; p++) {
                    float2 f = unpack2(acc[cc2 * 4 + p]);
                    w[cc2][2 * p] = f.x; w[cc2][2 * p + 1] = f.y;
                }
            }
            const int g0 = colbase + 4 * cg;
            float4 zea = *(const float4*)&zx_s[g0][0],     zeb = *(const float4*)&zx_s[g0][4];
            float4 zoa = *(const float4*)&zx_s[g0 + 1][0], zob = *(const float4*)&zx_s[g0 + 1][4];
            float4 zfa = *(const float4*)&zx_s[g0 + 2][0], zfb = *(const float4*)&zx_s[g0 + 2][4];
            float4 zga = *(const float4*)&zx_s[g0 + 3][0], zgb = *(const float4*)&zx_s[g0 + 3][4];
            float ze[8] = {zea.x, zea.y, zea.z, zea.w, zeb.x, zeb.y, zeb.z, zeb.w};
            float zo[8] = {zoa.x, zoa.y, zoa.z, zoa.w, zob.x, zob.y, zob.z, zob.w};
            float zf[8] = {zfa.x, zfa.y, zfa.z, zfa.w, zfb.x, zfb.y, zfb.z, zfb.w};
            float zg[8] = {zga.x, zga.y, zga.z, zga.w, zgb.x, zgb.y, zgb.z, zgb.w};

            float r[16];
            #pragma unroll
            for (int m = 0; m < MPER; m++) {
                float gA = ze[m] * w[1][m] - zo[m] * w[0][m];
                float gB = zf[m] * w[3][m] - zg[m] * w[2][m];
                r[2 * m]     = fmaf(omG00, gA, omG10 * gB);
                r[2 * m + 1] = fmaf(omG01, gA, omG11 * gB);
            }
            #pragma unroll
            for (int j = 0; j < 16; j++) {
                #pragma unroll
                for (int o = 16; o; o >>= 1)
                    r[j] += __shfl_xor_sync(0xFFFFFFFFu, r[j], o);
            }
            if (lane < 16) red_s[wid][lane] = r[lane];
        }
        __syncthreads();   // sync: red ready

        // ---- cross-CTA exchange of 16 dx partials ----
        const int buf = ts & 1;
        const uint32_t ph = (uint32_t)((ts >> 1) & 1);
        if (t < 16) {
            float v = red_s[0][t] + red_s[1][t];
            remote_st_f32(s2u(&peer_s[buf][t]), (uint32_t)prk, v);
            remote_arrive_rel(s2u(&mbar[buf]), (uint32_t)prk);
            mbar_wait_acq(s2u(&mbar[buf]), ph);
            float tot = v + peer_s[buf][t];
            const int m = t >> 1, j = t & 1;
            float dxt = dx_pi[((base + m) * TT + ts) * 2 + j] + ALPHA * tot;
            dxt_s[m][j] = dxt;
            float xn = x_s[m][j] + dxt;
            xn = fminf(fmaxf(xn, 0.0f), 2.0f);    // BOX_W == BOX_H == 2
            x_s[m][j] = xn;
            out_x[((base + m) * TT + ts) * 2 + j] = xn;
        }
        __syncthreads();   // sync: dxt ready

        // ---- phase 4: carried z' = T(dx_total) z ; write out_z ----
        #pragma unroll
        for (int mm = 0; mm < 4; mm++) {
            const int m = mg4 + mm;
            float th2 = fmaf(omB0, dxt_s[m][0], omB1 * dxt_s[m][1]);
            float s2, c2; fsincos(th2, &s2, &c2);
            float zp = __shfl_xor_sync(0xFFFFFFFFu, zc[mm], 1);
            float zn = (gcol & 1) ? fmaf(s2, zp, c2 * zc[mm])
                                  : fmaf(c2, zc[mm], -s2 * zp);
            zc[mm] = zn;
            out_z[((size_t)(base + m) * TT + ts) * DD + gcol] = zn;
        }
    }
}

extern "C" void kernel_launch(void* const* d_in, const int* in_sizes, int n_in,
                              void* d_out, int out_size) {
    (void)in_sizes; (void)n_in; (void)out_size;
    const float* dx_pi = (const float*)d_in[0];   // [512,128,2]
    const float* z0    = (const float*)d_in[1];   // [512,512]
    const float* x0    = (const float*)d_in[2];   // [512,2]
    const float* omega = (const float*)d_in[3];   // [256,2]
    const float* Ag    = (const float*)d_in[4];   // [512,512]
    const float* z0b   = (const float*)d_in[5];   // [512]

    float* out_z = (float*)d_out;                       // [512,128,512]
    float* out_x = out_z + (size_t)BB * TT * DD;        // [512,128,2]

    const size_t shmem = (size_t)ARC * CPC * sizeof(float)
                       + (size_t)8 * CSLOT * sizeof(ulonglong2);  // 128KB + 56KB
    cudaFuncSetAttribute(can_r9_kernel,
                         cudaFuncAttributeMaxDynamicSharedMemorySize, (int)shmem);
    can_r9_kernel<<<GCTA, NT, shmem>>>(dx_pi, z0, x0, omega, Ag, z0b,
                                       out_z, out_x);
}

// round 10
// speedup vs baseline: 1.5959x; 1.0355x over previous
#include <cuda_runtime.h>
#include <math.h>
#include <stdint.h>

// Problem constants
#define BB 512
#define TT 128
#define DD 512
#define ALPHA 0.1f
#define EPSN 1e-5f

// Config: 64 clusters x 2 CTAs; cluster handles 8 batch rows; CTA owns 256 cols.
#define CSZ 2
#define GCTA 128
#define MPER 8
#define NT 512
#define CPC 256          // columns per CTA
#define ARC 128          // A rows cached in smem (128KB); rq0,rq1 cached
#define NSEG 7           // combine segments (rq 1..7)
#define CSLOT (NSEG*64)  // 448 slots

typedef unsigned long long ull;

// ---- f32x2 helpers ----
static __device__ __forceinline__ ull packdup(float a) {
    ull r; asm("mov.b64 %0,{%1,%1};" : "=l"(r) : "f"(a)); return r;
}
static __device__ __forceinline__ void fma2(ull& d, ull a, ull b) {
    asm("fma.rn.f32x2 %0,%1,%2,%0;" : "+l"(d) : "l"(a), "l"(b));
}
static __device__ __forceinline__ ull add2(ull a, ull b) {
    ull r; asm("add.rn.f32x2 %0,%1,%2;" : "=l"(r) : "l"(a), "l"(b)); return r;
}
static __device__ __forceinline__ float2 unpack2(ull v) {
    float2 f; asm("mov.b64 {%0,%1},%2;" : "=f"(f.x), "=f"(f.y) : "l"(v)); return f;
}
static __device__ __forceinline__ uint32_t s2u(const void* p) {
    uint32_t a;
    asm("{.reg .u64 t; cvta.to.shared.u64 t,%1; cvt.u32.u64 %0,t;}" : "=r"(a) : "l"(p));
    return a;
}

// ---- named barriers ----
static __device__ __forceinline__ void nbar_sync(int id, int cnt) {
    asm volatile("bar.sync %0, %1;" :: "r"(id), "r"(cnt) : "memory");
}
static __device__ __forceinline__ void nbar_arrive(int id, int cnt) {
    asm volatile("bar.arrive %0, %1;" :: "r"(id), "r"(cnt) : "memory");
}

// ---- cluster mbarrier ops ----
static __device__ __forceinline__ void mbar_init(uint32_t a, uint32_t n) {
    asm volatile("mbarrier.init.shared.b64 [%0],%1;" :: "r"(a), "r"(n) : "memory");
}
static __device__ __forceinline__ void remote_st_f32(uint32_t a, uint32_t rk, float v) {
    asm volatile("{.reg .b32 r; mapa.shared::cluster.u32 r,%1,%2; st.shared::cluster.f32 [r],%0;}"
                 :: "f"(v), "r"(a), "r"(rk) : "memory");
}
static __device__ __forceinline__ void remote_arrive_rel(uint32_t a, uint32_t rk) {
    asm volatile("{.reg .b32 r; mapa.shared::cluster.u32 r,%0,%1;"
                 " mbarrier.arrive.release.cluster.shared::cluster.b64 _,[r];}"
                 :: "r"(a), "r"(rk) : "memory");
}
static __device__ __forceinline__ void mbar_wait_acq(uint32_t a, uint32_t ph) {
    asm volatile("{\n\t.reg .pred P;\n"
                 "W%=:\n\tmbarrier.try_wait.parity.acquire.cluster.shared::cta.b64 P,[%0],%1;\n"
                 "\t@P bra D%=;\n\tbra W%=;\nD%=:\n\t}"
                 :: "r"(a), "r"(ph) : "memory");
}

// fast sincos with explicit 2*pi range reduction
static __device__ __forceinline__ void fsincos(float th, float* s, float* c) {
    const float INV2PI = 0.15915494309189535f;
    const float TWOPI  = 6.283185307179586f;
    th = fmaf(-TWOPI, rintf(th * INV2PI), th);
    __sincosf(th, s, c);
}

// 16 packed FMAs: one A row (4 cols) against 8 m-values of zx
static __device__ __forceinline__ void rowfma(ull* acc, float4 b, const float* zrow) {
    ulonglong2 za = *(const ulonglong2*)(zrow);
    ulonglong2 zb = *(const ulonglong2*)(zrow + 4);
    ull z0 = za.x, z1 = za.y, z2 = zb.x, z3 = zb.y;
    ull d;
    d = packdup(b.x);
    fma2(acc[0], z0, d); fma2(acc[1], z1, d); fma2(acc[2], z2, d); fma2(acc[3], z3, d);
    d = packdup(b.y);
    fma2(acc[4], z0, d); fma2(acc[5], z1, d); fma2(acc[6], z2, d); fma2(acc[7], z3, d);
    d = packdup(b.z);
    fma2(acc[8], z0, d); fma2(acc[9], z1, d); fma2(acc[10], z2, d); fma2(acc[11], z3, d);
    d = packdup(b.w);
    fma2(acc[12], z0, d); fma2(acc[13], z1, d); fma2(acc[14], z2, d); fma2(acc[15], z3, d);
}

__global__ void __launch_bounds__(NT, 1) __cluster_dims__(CSZ, 1, 1)
can_r10_kernel(const float* __restrict__ dx_pi,   // [B,T,2]
               const float* __restrict__ z0,      // [B,D]
               const float* __restrict__ x0,      // [B,2]
               const float* __restrict__ omega,   // [K,2]
               const float* __restrict__ Ag,      // [D,D]
               const float* __restrict__ z0b,     // [D]
               float* __restrict__ out_z,         // [B,T,D]
               float* __restrict__ out_x)         // [B,T,2]
{
    // dynamic smem: As (128KB) then cbuf (56KB)
    extern __shared__ __align__(16) float As[];
    ulonglong2* cbuf = (ulonglong2*)(As + ARC * CPC);   // [8][CSLOT]

    __shared__ __align__(16) float zx_s[DD][MPER];      // 16KB
    __shared__ float red_s[2][16];
    __shared__ float nrm_s[16];
    __shared__ float x_s[MPER][2];
    __shared__ float dxt_s[MPER][2];
    __shared__ float peer_s[2][16];
    __shared__ __align__(8) ull mbar[2];
    __shared__ float scale_s;

    const int t    = threadIdx.x;
    const int lane = t & 31;
    const int wid  = t >> 5;
    const int rank = (int)(blockIdx.x & 1);
    const int prk  = rank ^ 1;
    const int colbase = rank * CPC;
    const int base = (int)(blockIdx.x >> 1) * MPER;

    // mainloop mapping: 64 col-groups (4 cols) x 8 row-blocks (64 rows)
    const int cg = t & 63;
    const int rq = t >> 6;

    // ---- preload A rows [0,ARC) cols [colbase,+256) into smem ----
    {
        const float4* src = (const float4*)Ag;
        float4* dst = (float4*)As;
        const int n4 = ARC * CPC / 4;
        for (int idx = t; idx < n4; idx += NT) {
            int row = idx >> 6;
            int f4  = idx & 63;
            dst[idx] = src[row * (DD / 4) + (colbase >> 2) + f4];
        }
    }
    if (t == 0) { mbar_init(s2u(&mbar[0]), 16); mbar_init(s2u(&mbar[1]), 16); }

    // ---- ||z0_base|| ----
    {
        float v = z0b[t]; v *= v;
        #pragma unroll
        for (int o = 16; o; o >>= 1) v += __shfl_xor_sync(0xFFFFFFFFu, v, o);
        if (lane == 0) nrm_s[wid] = v;
    }
    if (t < MPER * 2) x_s[t >> 1][t & 1] = x0[(base + (t >> 1)) * 2 + (t & 1)];
    __syncthreads();
    if (t == 0) {
        float s = 0.f;
        #pragma unroll
        for (int w = 0; w < 16; w++) s += nrm_s[w];
        scale_s = 1.0f / (sqrtf(s) + EPSN);
    }
    __syncthreads();

    // peer mbarriers initialized before any remote arrive
    asm volatile("barrier.cluster.arrive.aligned;" ::: "memory");
    asm volatile("barrier.cluster.wait.aligned;" ::: "memory");

    // ---- per-thread constants ----
    const int k1 = t & 255;
    const int mh = t >> 8;
    const float omA0 = omega[2 * k1];
    const float omA1 = omega[2 * k1 + 1];
    const float p0 = z0b[2 * k1] * scale_s;
    const float p1 = z0b[2 * k1 + 1] * scale_s;

    const int kb0 = rank * 128 + 2 * cg;
    const float omG00 = omega[2 * kb0],     omG01 = omega[2 * kb0 + 1];
    const float omG10 = omega[2 * kb0 + 2], omG11 = omega[2 * kb0 + 3];

    const int gcol = colbase + (t & 255);
    const int mg4  = (t >> 8) * 4;
    const float omB0 = omega[2 * (gcol >> 1)];
    const float omB1 = omega[2 * (gcol >> 1) + 1];

    // folded-butterfly output slot: bitrev4(lane & 15)
    const int brl = ((lane & 1) << 3) | ((lane & 2) << 1) |
                    ((lane & 4) >> 1) | ((lane & 8) >> 3);

    float zc[4];
    #pragma unroll
    for (int mm = 0; mm < 4; mm++)
        zc[mm] = z0[(base + mg4 + mm) * DD + gcol];

    const float4* As4 = (const float4*)As;                       // [row][64]
    const float4* Ag4 = (const float4*)Ag + (colbase >> 2) + cg; // row stride 128
    const int r0 = rq * 64;
    const bool cached = (rq < 2);          // rows 0..127 in smem

    // ---- initial prefetch of first 2 streamed batches ----
    float4 buf0[4], buf1[4];
    if (!cached) {
        #pragma unroll
        for (int q = 0; q < 4; q++) buf0[q] = __ldg(&Ag4[(r0 + q) * (DD / 4)]);
        #pragma unroll
        for (int q = 0; q < 4; q++) buf1[q] = __ldg(&Ag4[(r0 + 4 + q) * (DD / 4)]);
    }

    for (int ts = 0; ts < TT; ts++) {
        // ---- phase 1: zx = T(x_m) z0b_hat ----
        {
            float u0[4], u1[4];
            #pragma unroll
            for (int mm = 0; mm < 4; mm++) {
                int m = mh * 4 + mm;
                float th = fmaf(omA0, x_s[m][0], omA1 * x_s[m][1]);
                float s, ccv; fsincos(th, &s, &ccv);
                u0[mm] = fmaf(ccv, p0, -s * p1);
                u1[mm] = fmaf(s, p0, ccv * p1);
            }
            *(float4*)&zx_s[2 * k1][mh * 4]     = make_float4(u0[0], u0[1], u0[2], u0[3]);
            *(float4*)&zx_s[2 * k1 + 1][mh * 4] = make_float4(u1[0], u1[1], u1[2], u1[3]);
        }
        __syncthreads();   // sync A: zx ready

        // ---- phase 2: partial w over 64 rows x 4 cols x 8 m ----
        ull acc[16];
        #pragma unroll
        for (int q = 0; q < 16; q++) acc[q] = 0ull;

        if (cached) {
            #pragma unroll 4
            for (int i = r0; i < r0 + 64; i += 4) {
                float4 b0 = As4[(i + 0) * 64 + cg];
                float4 b1 = As4[(i + 1) * 64 + cg];
                float4 b2 = As4[(i + 2) * 64 + cg];
                float4 b3 = As4[(i + 3) * 64 + cg];
                rowfma(acc, b0, &zx_s[i + 0][0]);
                rowfma(acc, b1, &zx_s[i + 1][0]);
                rowfma(acc, b2, &zx_s[i + 2][0]);
                rowfma(acc, b3, &zx_s[i + 3][0]);
            }
        } else {
            // depth-2 software pipeline over 16 batches of 4 rows
            #pragma unroll
            for (int b = 0; b < 16; b++) {
                const int i = r0 + 4 * b;
                float4 c0, c1, c2, c3;
                if ((b & 1) == 0) { c0 = buf0[0]; c1 = buf0[1]; c2 = buf0[2]; c3 = buf0[3]; }
                else              { c0 = buf1[0]; c1 = buf1[1]; c2 = buf1[2]; c3 = buf1[3]; }
                if (b < 14) {
                    const int ip = i + 8;
                    if ((b & 1) == 0) {
                        #pragma unroll
                        for (int q = 0; q < 4; q++)
                            buf0[q] = __ldg(&Ag4[(ip + q) * (DD / 4)]);
                    } else {
                        #pragma unroll
                        for (int q = 0; q < 4; q++)
                            buf1[q] = __ldg(&Ag4[(ip + q) * (DD / 4)]);
                    }
                }
                rowfma(acc, c0, &zx_s[i + 0][0]);
                rowfma(acc, c1, &zx_s[i + 1][0]);
                rowfma(acc, c2, &zx_s[i + 2][0]);
                rowfma(acc, c3, &zx_s[i + 3][0]);
            }
        }

        // ---- split tail: writers stage + arrive + prefetch; rq0 reduces ----
        if (rq >= 1) {
            const int slot = (rq - 1) * 64 + cg;
            #pragma unroll
            for (int j = 0; j < 8; j++)
                cbuf[j * CSLOT + slot] = make_ulonglong2(acc[2 * j], acc[2 * j + 1]);
            nbar_arrive(1, NT);            // release partials to rq0
            // prefetch next step's first 2 batches (A is step-invariant);
            // overlaps the entire combine/exchange tail
            if (!cached) {
                #pragma unroll
                for (int q = 0; q < 4; q++) buf0[q] = __ldg(&Ag4[(r0 + q) * (DD / 4)]);
                #pragma unroll
                for (int q = 0; q < 4; q++) buf1[q] = __ldg(&Ag4[(r0 + 4 + q) * (DD / 4)]);
            }
        } else {
            nbar_sync(1, NT);              // wait for all partials
            #pragma unroll
            for (int seg = 0; seg < NSEG; seg++) {
                const int slot = seg * 64 + cg;
                #pragma unroll
                for (int j = 0; j < 8; j++) {
                    ulonglong2 v = cbuf[j * CSLOT + slot];
                    acc[2 * j]     = add2(acc[2 * j], v.x);
                    acc[2 * j + 1] = add2(acc[2 * j + 1], v.y);
                }
            }
            float w[4][8];
            #pragma unroll
            for (int cc2 = 0; cc2 < 4; cc2++) {
                #pragma unroll
                for (int p = 0; p < 4; p++) {
                    float2 f = unpack2(acc[cc2 * 4 + p]);
                    w[cc2][2 * p] = f.x; w[cc2][2 * p + 1] = f.y;
                }
            }
            const int g0 = colbase + 4 * cg;
            float4 zea = *(const float4*)&zx_s[g0][0],     zeb = *(const float4*)&zx_s[g0][4];
            float4 zoa = *(const float4*)&zx_s[g0 + 1][0], zob = *(const float4*)&zx_s[g0 + 1][4];
            float4 zfa = *(const float4*)&zx_s[g0 + 2][0], zfb = *(const float4*)&zx_s[g0 + 2][4];
            float4 zga = *(const float4*)&zx_s[g0 + 3][0], zgb = *(const float4*)&zx_s[g0 + 3][4];
            float ze[8] = {zea.x, zea.y, zea.z, zea.w, zeb.x, zeb.y, zeb.z, zeb.w};
            float zo[8] = {zoa.x, zoa.y, zoa.z, zoa.w, zob.x, zob.y, zob.z, zob.w};
            float zf[8] = {zfa.x, zfa.y, zfa.z, zfa.w, zfb.x, zfb.y, zfb.z, zfb.w};
            float zg[8] = {zga.x, zga.y, zga.z, zga.w, zgb.x, zgb.y, zgb.z, zgb.w};

            float r[16];
            #pragma unroll
            for (int m = 0; m < MPER; m++) {
                float gA = ze[m] * w[1][m] - zo[m] * w[0][m];
                float gB = zf[m] * w[3][m] - zg[m] * w[2][m];
                r[2 * m]     = fmaf(omG00, gA, omG10 * gB);
                r[2 * m + 1] = fmaf(omG01, gA, omG11 * gB);
            }
            // folding butterfly: 16 values x 32 lanes -> 1/lane (16 SHFL)
            #pragma unroll
            for (int o = 1, v = 16; o <= 8; o <<= 1, v >>= 1) {
                const bool hi = (lane & o) != 0;
                #pragma unroll
                for (int i = 0; i < v / 2; i++) {
                    float send = hi ? r[i] : r[i + v / 2];
                    float recv = __shfl_xor_sync(0xFFFFFFFFu, send, o);
                    float keep = hi ? r[i + v / 2] : r[i];
                    r[i] = keep + recv;
                }
            }
            r[0] += __shfl_xor_sync(0xFFFFFFFFu, r[0], 16);
            if (lane < 16) red_s[wid][brl] = r[0];

            nbar_sync(2, 64);              // warps 0-1 handoff only

            // cross-CTA exchange of 16 dx partials
            const int buf = ts & 1;
            const uint32_t ph = (uint32_t)((ts >> 1) & 1);
            if (t < 16) {
                float v = red_s[0][t] + red_s[1][t];
                remote_st_f32(s2u(&peer_s[buf][t]), (uint32_t)prk, v);
                remote_arrive_rel(s2u(&mbar[buf]), (uint32_t)prk);
                const int m = t >> 1, j = t & 1;
                float dpi = __ldg(&dx_pi[((base + m) * TT + ts) * 2 + j]);
                mbar_wait_acq(s2u(&mbar[buf]), ph);
                float tot = v + peer_s[buf][t];
                float dxt = dpi + ALPHA * tot;
                dxt_s[m][j] = dxt;
                float xn = x_s[m][j] + dxt;
                xn = fminf(fmaxf(xn, 0.0f), 2.0f);   // BOX_W == BOX_H == 2
                x_s[m][j] = xn;
                out_x[((base + m) * TT + ts) * 2 + j] = xn;
            }
        }
        __syncthreads();   // sync C: dxt ready (and zx_s safe to overwrite)

        // ---- phase 4: carried z' = T(dx_total) z ; write out_z ----
        #pragma unroll
        for (int mm = 0; mm < 4; mm++) {
            const int m = mg4 + mm;
            float th2 = fmaf(omB0, dxt_s[m][0], omB1 * dxt_s[m][1]);
            float s2, c2; fsincos(th2, &s2, &c2);
            float zp = __shfl_xor_sync(0xFFFFFFFFu, zc[mm], 1);
            float zn = (gcol & 1) ? fmaf(s2, zp, c2 * zc[mm])
                                  : fmaf(c2, zc[mm], -s2 * zp);
            zc[mm] = zn;
            out_z[((size_t)(base + m) * TT + ts) * DD + gcol] = zn;
        }
    }
}

extern "C" void kernel_launch(void* const* d_in, const int* in_sizes, int n_in,
                              void* d_out, int out_size) {
    (void)in_sizes; (void)n_in; (void)out_size;
    const float* dx_pi = (const float*)d_in[0];   // [512,128,2]
    const float* z0    = (const float*)d_in[1];   // [512,512]
    const float* x0    = (const float*)d_in[2];   // [512,2]
    const float* omega = (const float*)d_in[3];   // [256,2]
    const float* Ag    = (const float*)d_in[4];   // [512,512]
    const float* z0b   = (const float*)d_in[5];   // [512]

    float* out_z = (float*)d_out;                       // [512,128,512]
    float* out_x = out_z + (size_t)BB * TT * DD;        // [512,128,2]

    const size_t shmem = (size_t)ARC * CPC * sizeof(float)
                       + (size_t)8 * CSLOT * sizeof(ulonglong2);  // 128KB + 56KB
    cudaFuncSetAttribute(can_r10_kernel,
                         cudaFuncAttributeMaxDynamicSharedMemorySize, (int)shmem);
    can_r10_kernel<<<GCTA, NT, shmem>>>(dx_pi, z0, x0, omega, Ag, z0b,
                                        out_z, out_x);
}